// round 4
// baseline (speedup 1.0000x reference)
#include <cuda_runtime.h>
#include <cstdint>
#include <cstddef>

#define BB 64
#define TT 512
#define AA 128
#define HH 512
#define G4 2048  // 4*H
#define NCTA 128
#define STEPS_PER_KERNEL 128

// ---------------- scratch (static device allocations) ----------------
__device__ float g_pre[(size_t)TT * G4 * BB];   // 256MB: pre-gates [t][row 2048][b 64]  (TRANSPOSED)
__device__ float g_hall[(size_t)TT * BB * HH];  // 64MB : h history [t][b][H]
__device__ float g_h[2 * BB * HH];              // double-buffered recurrent h [buf][b][H]
__device__ float g_c[BB * HH];                  // cell state carry between sub-kernels
__device__ float g_wp[(size_t)BB * AA * HH];    // 16MB : W'[b]
__device__ unsigned g_flag[NCTA];               // epoch flags (monotone; compared relatively)

__device__ __forceinline__ void st_rel(unsigned* p, unsigned v) {
    asm volatile("st.release.gpu.global.u32 [%0], %1;" :: "l"(p), "r"(v) : "memory");
}
__device__ __forceinline__ unsigned ld_acq(const unsigned* p) {
    unsigned v;
    asm volatile("ld.acquire.gpu.global.u32 %0, [%1];" : "=r"(v) : "l"(p) : "memory");
    return v;
}

// ---------------- kernel 1: pre[t][row][b] = bias[row] + x[b][t] . w_ih[row] (transposed store) ----
__global__ __launch_bounds__(256) void k_pregates(const float* __restrict__ x,
                                                  const float* __restrict__ w_ih,
                                                  const float* __restrict__ b_ih,
                                                  const float* __restrict__ b_hh) {
    __shared__ float As[64][68];
    __shared__ float Bs[64][68];
    const int t  = blockIdx.y;
    const int n0 = blockIdx.x * 64;
    const int tid = threadIdx.x;
    const int tm = tid >> 4;
    const int tn = tid & 15;
    float acc[4][4] = {};

    for (int k0 = 0; k0 < AA; k0 += 64) {
#pragma unroll
        for (int i = 0; i < 4; i++) {
            int id = tid + i * 256;
            int r = id >> 4, c4 = (id & 15) << 2;
            *(float4*)&As[r][c4] = *(const float4*)&x[((size_t)r * TT + t) * AA + k0 + c4];
            *(float4*)&Bs[r][c4] = *(const float4*)&w_ih[(size_t)(n0 + r) * AA + k0 + c4];
        }
        __syncthreads();
#pragma unroll
        for (int k = 0; k < 64; k += 4) {
            float4 a[4], b[4];
#pragma unroll
            for (int i = 0; i < 4; i++) a[i] = *(const float4*)&As[tm * 4 + i][k];
#pragma unroll
            for (int j = 0; j < 4; j++) b[j] = *(const float4*)&Bs[tn * 4 + j][k];
#pragma unroll
            for (int i = 0; i < 4; i++)
#pragma unroll
                for (int j = 0; j < 4; j++)
                    acc[i][j] += a[i].x * b[j].x + a[i].y * b[j].y + a[i].z * b[j].z + a[i].w * b[j].w;
        }
        __syncthreads();
    }
    float4 bi = *(const float4*)&b_ih[n0 + tn * 4];
    float4 bh = *(const float4*)&b_hh[n0 + tn * 4];
    float bias[4] = {bi.x + bh.x, bi.y + bh.y, bi.z + bh.z, bi.w + bh.w};
#pragma unroll
    for (int j = 0; j < 4; j++) {
        float4 v = make_float4(acc[0][j] + bias[j], acc[1][j] + bias[j],
                               acc[2][j] + bias[j], acc[3][j] + bias[j]);
        *(float4*)&g_pre[((size_t)t * G4 + n0 + tn * 4 + j) * BB + tm * 4] = v;
    }
}

// ---------------- kernel 2: W'[b] = w_out + w_out @ M[b] ----------------
__global__ __launch_bounds__(256) void k_wprime(const float* __restrict__ w_out,
                                                const float* __restrict__ Mm) {
    __shared__ float As[64][68];
    __shared__ float Bs[64][68];
    const int b  = blockIdx.z;
    const int m0 = blockIdx.y * 64;
    const int n0 = blockIdx.x * 64;
    const int tid = threadIdx.x;
    const int tm = tid >> 4, tn = tid & 15;
    float acc[4][4] = {};

    for (int k0 = 0; k0 < HH; k0 += 64) {
#pragma unroll
        for (int i = 0; i < 4; i++) {
            int id = tid + i * 256;
            int r = id >> 4, c4 = (id & 15) << 2;
            *(float4*)&As[r][c4] = *(const float4*)&w_out[(size_t)(m0 + r) * HH + k0 + c4];
            *(float4*)&Bs[r][c4] = *(const float4*)&Mm[((size_t)b * HH + k0 + r) * HH + n0 + c4];
        }
        __syncthreads();
#pragma unroll
        for (int k = 0; k < 64; k += 4) {
            float4 a[4];
#pragma unroll
            for (int i = 0; i < 4; i++) a[i] = *(const float4*)&As[tm * 4 + i][k];
#pragma unroll
            for (int kk = 0; kk < 4; kk++) {
                float4 bv = *(const float4*)&Bs[k + kk][tn * 4];
#pragma unroll
                for (int i = 0; i < 4; i++) {
                    float av = (kk == 0) ? a[i].x : (kk == 1) ? a[i].y : (kk == 2) ? a[i].z : a[i].w;
                    acc[i][0] += av * bv.x; acc[i][1] += av * bv.y;
                    acc[i][2] += av * bv.z; acc[i][3] += av * bv.w;
                }
            }
        }
        __syncthreads();
    }
#pragma unroll
    for (int i = 0; i < 4; i++) {
        int m = m0 + tm * 4 + i;
        float4 w0 = *(const float4*)&w_out[(size_t)m * HH + n0 + tn * 4];
        float4 v = make_float4(acc[i][0] + w0.x, acc[i][1] + w0.y,
                               acc[i][2] + w0.z, acc[i][3] + w0.w);
        *(float4*)&g_wp[((size_t)b * AA + m) * HH + n0 + tn * 4] = v;
    }
}

// ---------------- kernel 3: persistent recurrent loop (128 steps per launch) ------------
// 128 CTAs x 256 thr. CTA owns 4 hidden units -> 16 w_hh rows resident in smem,
// TRANSPOSED as wt[k][row]. h staged per chunk transposed hs[k][b] (LDS.128-friendly).
// Thread tile: 4 b x 2 rows, k split in 2 segments (smem-reduced).
// Flag-based release/acquire grid barrier between steps.
__global__ __launch_bounds__(256) void k_loop(const float* __restrict__ w_hh,
                                              const float* __restrict__ h0,
                                              const float* __restrict__ c0,
                                              int t0) {
    extern __shared__ float sm[];
    float* wt   = sm;                       // [512][16]   8192 floats
    float* hs   = sm + 8192;                // [2][64][64] 8192 floats
    float* gbuf = sm + 16384;               // [64][17]    1088 floats
    float* rbuf = sm + 16384 + 1088;        // [128][8]    1024 floats (also hres reuse)

    const int tid = threadIdx.x;
    const int bid = blockIdx.x;
    const int j0  = bid * 4;

    // ---- load w rows transposed: wt[k*16 + row] ----
    for (int idx = tid; idx < 16 * 512; idx += 256) {
        int row = idx & 15, k = idx >> 4;
        int g = row >> 2, jj = row & 3;
        wt[k * 16 + row] = w_hh[(size_t)(g * HH + j0 + jj) * HH + k];
    }

    // ---- compute mapping: 4b x 2rows tile, 2-way k-split ----
    const int bg = tid & 15;            // b-group (4 b)
    const int rg = (tid >> 4) & 7;      // row-pair
    const int ks = tid >> 7;            // k segment 0/1
    const int r0 = rg * 2, r1 = r0 + 1;
    const size_t rowg0 = (size_t)((r0 >> 2) * HH + j0 + (r0 & 3));
    const size_t rowg1 = (size_t)((r1 >> 2) * HH + j0 + (r1 & 3));

    // ---- staging mapping ----
    const int sb = tid & 63;
    const int sk = (tid >> 6) << 4;

    // ---- pointwise mapping; c carried in register across steps ----
    const int pb = tid & 63, pjj = tid >> 6;
    const int pidx = pb * HH + j0 + pjj;
    float c_reg = (t0 == 0) ? c0[pidx] : g_c[pidx];

    const unsigned e0 = ld_acq(&g_flag[bid]);
    __syncthreads();

    for (int s = 0; s < STEPS_PER_KERNEL; ++s) {
        const int t = t0 + s;
        if (s > 0) {   // wait for all CTAs to publish h(t)
            if (tid < NCTA) {
                const unsigned target = e0 + (unsigned)s;
                while ((int)(ld_acq(&g_flag[tid]) - target) < 0) {}
            }
            __syncthreads();
        }
        const float* hsrc  = (t == 0) ? h0 : (g_h + (size_t)(t & 1) * BB * HH);
        const float* pre_t = g_pre + (size_t)t * G4 * BB;

        // prefetch coalesced pre (latency hidden behind GEMM)
        float4 pr0 = __ldg((const float4*)&pre_t[rowg0 * BB + bg * 4]);
        float4 pr1 = __ldg((const float4*)&pre_t[rowg1 * BB + bg * 4]);

        // stage chunk 0 (transposed hs[k][b])
        {
            const float* row = hsrc + sb * HH;
#pragma unroll
            for (int j = 0; j < 4; j++) {
                float4 v = __ldcg((const float4*)(row + sk + j * 4));
                float* d = hs + (sk + j * 4) * 64 + sb;
                d[0] = v.x; d[64] = v.y; d[128] = v.z; d[192] = v.w;
            }
        }
        __syncthreads();

        float4 a0 = {0.f, 0.f, 0.f, 0.f}, a1 = {0.f, 0.f, 0.f, 0.f};
#pragma unroll 1
        for (int c = 0; c < 8; ++c) {
            float4 pf[4];
            if (c < 7) {
                const float* row = hsrc + sb * HH + (c + 1) * 64;
#pragma unroll
                for (int j = 0; j < 4; j++)
                    pf[j] = __ldcg((const float4*)(row + sk + j * 4));
            }
            const float* hb = hs + (c & 1) * 4096 + ks * (32 * 64) + bg * 4;
            const float* wp = wt + (c * 64 + ks * 32) * 16 + rg * 2;
#pragma unroll
            for (int kk = 0; kk < 32; ++kk) {
                float4 h4 = *(const float4*)(hb + kk * 64);
                float2 w2 = *(const float2*)(wp + kk * 16);
                a0.x += h4.x * w2.x; a0.y += h4.y * w2.x;
                a0.z += h4.z * w2.x; a0.w += h4.w * w2.x;
                a1.x += h4.x * w2.y; a1.y += h4.y * w2.y;
                a1.z += h4.z * w2.y; a1.w += h4.w * w2.y;
            }
            if (c < 7) {
                float* d = hs + ((c + 1) & 1) * 4096 + sk * 64 + sb;
#pragma unroll
                for (int j = 0; j < 4; j++) {
                    d[(j * 4 + 0) * 64] = pf[j].x;
                    d[(j * 4 + 1) * 64] = pf[j].y;
                    d[(j * 4 + 2) * 64] = pf[j].z;
                    d[(j * 4 + 3) * 64] = pf[j].w;
                }
            }
            __syncthreads();
        }

        // ---- k-segment reduction (ks==1 publishes partials) ----
        if (ks == 1) {
            float* rb = rbuf + (tid & 127) * 8;
            *(float4*)rb       = a0;
            *(float4*)(rb + 4) = a1;
        }
        __syncthreads();
        if (ks == 0) {
            const float* rb = rbuf + tid * 8;
            float4 b0 = *(const float4*)rb, b1 = *(const float4*)(rb + 4);
            a0.x += b0.x; a0.y += b0.y; a0.z += b0.z; a0.w += b0.w;
            a1.x += b1.x; a1.y += b1.y; a1.z += b1.z; a1.w += b1.w;
            int bb0 = bg * 4;
            gbuf[(bb0 + 0) * 17 + r0] = a0.x + pr0.x;
            gbuf[(bb0 + 1) * 17 + r0] = a0.y + pr0.y;
            gbuf[(bb0 + 2) * 17 + r0] = a0.z + pr0.z;
            gbuf[(bb0 + 3) * 17 + r0] = a0.w + pr0.w;
            gbuf[(bb0 + 0) * 17 + r1] = a1.x + pr1.x;
            gbuf[(bb0 + 1) * 17 + r1] = a1.y + pr1.y;
            gbuf[(bb0 + 2) * 17 + r1] = a1.z + pr1.z;
            gbuf[(bb0 + 3) * 17 + r1] = a1.w + pr1.w;
        }
        __syncthreads();

        // ---- LSTM pointwise; result regrouped in smem for coalesced writeback ----
        {
            float xi = gbuf[pb * 17 + pjj];
            float xf = gbuf[pb * 17 + 4 + pjj];
            float xg = gbuf[pb * 17 + 8 + pjj];
            float xo = gbuf[pb * 17 + 12 + pjj];
            float si = 1.0f / (1.0f + __expf(-xi));
            float sf = 1.0f / (1.0f + __expf(-xf));
            float so = 1.0f / (1.0f + __expf(-xo));
            float tg = tanhf(xg);
            c_reg = sf * c_reg + si * tg;
            float hn = so * tanhf(c_reg);
            rbuf[pjj * 64 + pb] = hn;   // hres reuse of rbuf
        }
        __syncthreads();
        if (tid < 64) {   // one float4 (4 hidden units) per batch -> coalesced-ish 16B stores
            float4 hv = make_float4(rbuf[0 * 64 + tid], rbuf[1 * 64 + tid],
                                    rbuf[2 * 64 + tid], rbuf[3 * 64 + tid]);
            const int base = tid * HH + j0;
            __stcg((float4*)(g_h + (size_t)((t + 1) & 1) * BB * HH + base), hv);
            __stcg((float4*)(g_hall + (size_t)t * BB * HH + base), hv);
        }
        __syncthreads();
        if (tid == 0) st_rel(&g_flag[bid], e0 + (unsigned)(s + 1));
    }

    g_c[pidx] = c_reg;   // carry cell state to next sub-kernel
}

// ---------------- kernel 4: out[b][t][a] = h_all[t][b] . W'[b][a] + b_out[a] ----------
__global__ __launch_bounds__(256) void k_out(const float* __restrict__ b_out,
                                             float* __restrict__ out) {
    __shared__ float As[64][68];
    __shared__ float Bs[64][68];
    const int b  = blockIdx.z;
    const int m0 = blockIdx.y * 64;
    const int n0 = blockIdx.x * 64;
    const int tid = threadIdx.x;
    const int tm = tid >> 4, tn = tid & 15;
    float acc[4][4] = {};

    for (int k0 = 0; k0 < HH; k0 += 64) {
#pragma unroll
        for (int i = 0; i < 4; i++) {
            int id = tid + i * 256;
            int r = id >> 4, c4 = (id & 15) << 2;
            *(float4*)&As[r][c4] = *(const float4*)&g_hall[((size_t)(m0 + r) * BB + b) * HH + k0 + c4];
            *(float4*)&Bs[r][c4] = *(const float4*)&g_wp[((size_t)b * AA + n0 + r) * HH + k0 + c4];
        }
        __syncthreads();
#pragma unroll
        for (int k = 0; k < 64; k += 4) {
            float4 a[4], bv[4];
#pragma unroll
            for (int i = 0; i < 4; i++) a[i] = *(const float4*)&As[tm * 4 + i][k];
#pragma unroll
            for (int j = 0; j < 4; j++) bv[j] = *(const float4*)&Bs[tn * 4 + j][k];
#pragma unroll
            for (int i = 0; i < 4; i++)
#pragma unroll
                for (int j = 0; j < 4; j++)
                    acc[i][j] += a[i].x * bv[j].x + a[i].y * bv[j].y + a[i].z * bv[j].z + a[i].w * bv[j].w;
        }
        __syncthreads();
    }
    float4 bo = *(const float4*)&b_out[n0 + tn * 4];
#pragma unroll
    for (int i = 0; i < 4; i++) {
        int m = m0 + tm * 4 + i;
        float4 v = make_float4(acc[i][0] + bo.x, acc[i][1] + bo.y,
                               acc[i][2] + bo.z, acc[i][3] + bo.w);
        *(float4*)&out[((size_t)b * TT + m) * AA + n0 + tn * 4] = v;
    }
}

// ---------------- launch ----------------
extern "C" void kernel_launch(void* const* d_in, const int* in_sizes, int n_in,
                              void* d_out, int out_size) {
    const float* x     = (const float*)d_in[0];
    const float* w_ih  = (const float*)d_in[1];
    const float* w_hh  = (const float*)d_in[2];
    const float* b_ih  = (const float*)d_in[3];
    const float* b_hh  = (const float*)d_in[4];
    const float* Mm    = (const float*)d_in[5];
    const float* w_out = (const float*)d_in[6];
    const float* b_out = (const float*)d_in[7];
    const float* h0    = (const float*)d_in[8];
    const float* c0    = (const float*)d_in[9];
    float* out = (float*)d_out;

    const int loop_smem = (8192 + 8192 + 1088 + 1024) * sizeof(float);  // ~74 KB
    static int attr_done = 0;
    if (!attr_done) {
        cudaFuncSetAttribute(k_loop, cudaFuncAttributeMaxDynamicSharedMemorySize, loop_smem);
        attr_done = 1;
    }

    k_pregates<<<dim3(G4 / 64, TT), 256>>>(x, w_ih, b_ih, b_hh);
    k_wprime<<<dim3(HH / 64, AA / 64, BB), 256>>>(w_out, Mm);

    for (int t0 = 0; t0 < TT; t0 += STEPS_PER_KERNEL)
        k_loop<<<NCTA, 256, loop_smem>>>(w_hh, h0, c0, t0);

    k_out<<<dim3(AA / 64, TT / 64, BB), 256>>>(b_out, out);
}

// round 5
// speedup vs baseline: 1.3976x; 1.3976x over previous
#include <cuda_runtime.h>
#include <cstdint>
#include <cstddef>

#define BB 64
#define TT 512
#define AA 128
#define HH 512
#define G4 2048  // 4*H
#define NCTA 128

typedef unsigned long long ull;

// ---------------- scratch (static device allocations) ----------------
__device__ float g_pre[(size_t)TT * G4 * BB];   // 256MB: pre-gates [t][row][b]  (transposed)
__device__ float g_hall[(size_t)TT * BB * HH];  // 64MB : h history [t][b][H]
__device__ float g_hT[2][HH * BB];              // recurrent h, TRANSPOSED [buf][k][b]
__device__ float g_wp[(size_t)BB * AA * HH];    // 16MB : W'[b]
__device__ unsigned g_flag[NCTA];               // epoch flags (monotone, relative compare)

__device__ __forceinline__ void st_rel(unsigned* p, unsigned v) {
    asm volatile("st.release.gpu.global.u32 [%0], %1;" :: "l"(p), "r"(v) : "memory");
}
__device__ __forceinline__ unsigned ld_acq(const unsigned* p) {
    unsigned v;
    asm volatile("ld.acquire.gpu.global.u32 %0, [%1];" : "=r"(v) : "l"(p) : "memory");
    return v;
}
__device__ __forceinline__ ull fma2(ull a, ull b, ull c) {
    ull d;
    asm("fma.rn.f32x2 %0, %1, %2, %3;" : "=l"(d) : "l"(a), "l"(b), "l"(c));
    return d;
}
__device__ __forceinline__ ull add2(ull a, ull b) {
    ull d;
    asm("add.rn.f32x2 %0, %1, %2;" : "=l"(d) : "l"(a), "l"(b));
    return d;
}
__device__ __forceinline__ float2 unpack2(ull v) {
    float lo, hi;
    asm("mov.b64 {%0, %1}, %2;" : "=f"(lo), "=f"(hi) : "l"(v));
    return make_float2(lo, hi);
}

// ---------------- kernel 0: transpose h0 into g_hT[0] ----------------
__global__ void k_init(const float* __restrict__ h0) {
    int id = blockIdx.x * blockDim.x + threadIdx.x;   // 128 blocks x 256
    int b = id & 63, k = id >> 6;
    g_hT[0][k * BB + b] = h0[b * HH + k];
}

// ---------------- kernel 1: pre[t][row][b] (transposed store) ----------------
__global__ __launch_bounds__(256) void k_pregates(const float* __restrict__ x,
                                                  const float* __restrict__ w_ih,
                                                  const float* __restrict__ b_ih,
                                                  const float* __restrict__ b_hh) {
    __shared__ float As[64][68];
    __shared__ float Bs[64][68];
    const int t  = blockIdx.y;
    const int n0 = blockIdx.x * 64;
    const int tid = threadIdx.x;
    const int tm = tid >> 4;
    const int tn = tid & 15;
    float acc[4][4] = {};

    for (int k0 = 0; k0 < AA; k0 += 64) {
#pragma unroll
        for (int i = 0; i < 4; i++) {
            int id = tid + i * 256;
            int r = id >> 4, c4 = (id & 15) << 2;
            *(float4*)&As[r][c4] = *(const float4*)&x[((size_t)r * TT + t) * AA + k0 + c4];
            *(float4*)&Bs[r][c4] = *(const float4*)&w_ih[(size_t)(n0 + r) * AA + k0 + c4];
        }
        __syncthreads();
#pragma unroll
        for (int k = 0; k < 64; k += 4) {
            float4 a[4], b[4];
#pragma unroll
            for (int i = 0; i < 4; i++) a[i] = *(const float4*)&As[tm * 4 + i][k];
#pragma unroll
            for (int j = 0; j < 4; j++) b[j] = *(const float4*)&Bs[tn * 4 + j][k];
#pragma unroll
            for (int i = 0; i < 4; i++)
#pragma unroll
                for (int j = 0; j < 4; j++)
                    acc[i][j] += a[i].x * b[j].x + a[i].y * b[j].y + a[i].z * b[j].z + a[i].w * b[j].w;
        }
        __syncthreads();
    }
    float4 bi = *(const float4*)&b_ih[n0 + tn * 4];
    float4 bh = *(const float4*)&b_hh[n0 + tn * 4];
    float bias[4] = {bi.x + bh.x, bi.y + bh.y, bi.z + bh.z, bi.w + bh.w};
#pragma unroll
    for (int j = 0; j < 4; j++) {
        float4 v = make_float4(acc[0][j] + bias[j], acc[1][j] + bias[j],
                               acc[2][j] + bias[j], acc[3][j] + bias[j]);
        *(float4*)&g_pre[((size_t)t * G4 + n0 + tn * 4 + j) * BB + tm * 4] = v;
    }
}

// ---------------- kernel 2: W'[b] = w_out + w_out @ M[b] ----------------
__global__ __launch_bounds__(256) void k_wprime(const float* __restrict__ w_out,
                                                const float* __restrict__ Mm) {
    __shared__ float As[64][68];
    __shared__ float Bs[64][68];
    const int b  = blockIdx.z;
    const int m0 = blockIdx.y * 64;
    const int n0 = blockIdx.x * 64;
    const int tid = threadIdx.x;
    const int tm = tid >> 4, tn = tid & 15;
    float acc[4][4] = {};

    for (int k0 = 0; k0 < HH; k0 += 64) {
#pragma unroll
        for (int i = 0; i < 4; i++) {
            int id = tid + i * 256;
            int r = id >> 4, c4 = (id & 15) << 2;
            *(float4*)&As[r][c4] = *(const float4*)&w_out[(size_t)(m0 + r) * HH + k0 + c4];
            *(float4*)&Bs[r][c4] = *(const float4*)&Mm[((size_t)b * HH + k0 + r) * HH + n0 + c4];
        }
        __syncthreads();
#pragma unroll
        for (int k = 0; k < 64; k += 4) {
            float4 a[4];
#pragma unroll
            for (int i = 0; i < 4; i++) a[i] = *(const float4*)&As[tm * 4 + i][k];
#pragma unroll
            for (int kk = 0; kk < 4; kk++) {
                float4 bv = *(const float4*)&Bs[k + kk][tn * 4];
#pragma unroll
                for (int i = 0; i < 4; i++) {
                    float av = (kk == 0) ? a[i].x : (kk == 1) ? a[i].y : (kk == 2) ? a[i].z : a[i].w;
                    acc[i][0] += av * bv.x; acc[i][1] += av * bv.y;
                    acc[i][2] += av * bv.z; acc[i][3] += av * bv.w;
                }
            }
        }
        __syncthreads();
    }
#pragma unroll
    for (int i = 0; i < 4; i++) {
        int m = m0 + tm * 4 + i;
        float4 w0 = *(const float4*)&w_out[(size_t)m * HH + n0 + tn * 4];
        float4 v = make_float4(acc[i][0] + w0.x, acc[i][1] + w0.y,
                               acc[i][2] + w0.z, acc[i][3] + w0.w);
        *(float4*)&g_wp[((size_t)b * AA + m) * HH + n0 + tn * 4] = v;
    }
}

// ---------------- kernel 3: persistent recurrent loop, all 512 steps ----------------
// 128 CTAs x 512 threads. CTA owns 4 hidden units (16 gate rows).
// w resident in smem, duplicated-pair layout wtd[k][32] = (w_r0,w_r0,w_r1,w_r1,...).
// h staged whole each step into hs[k][b] (linear copy from g_hT). FFMA2 inner loop.
// Thread tile: (bg 0..15) x (rgp 0..7) x (ks 0..3): 4 batches x 2 rows x 128 k.
__global__ __launch_bounds__(512) void k_loop(const float* __restrict__ w_hh,
                                              const float* __restrict__ c0) {
    extern __shared__ float sm[];
    float* wtd  = sm;                     // [512][32]        16384 f (64KB)
    float* hs   = sm + 16384;             // [512][64]        32768 f (128KB)
    float* rbuf = sm + 16384 + 32768;     // [128][3][8]      3072 f (12KB)
    float* gbuf = rbuf + 3072;            // [64][17]         1088 f
    float* hres = gbuf + 1088;            // [4][64]          256 f

    const int tid = threadIdx.x;
    const int bid = blockIdx.x;
    const int j0  = bid * 4;

    // ---- load w rows, duplicated pairs: wtd[k*32 + row*2 {+0,+1}] ----
    for (int idx = tid; idx < 16 * 512; idx += 512) {
        int row = idx & 15, k = idx >> 4;
        int g = row >> 2, jj = row & 3;
        float v = w_hh[(size_t)(g * HH + j0 + jj) * HH + k];
        wtd[k * 32 + row * 2]     = v;
        wtd[k * 32 + row * 2 + 1] = v;
    }

    // ---- compute mapping ----
    const int bg  = tid & 15;           // 4-batch group
    const int rgp = (tid >> 4) & 7;     // row pair: rows 2*rgp, 2*rgp+1
    const int ks  = tid >> 7;           // k segment (128 k each)
    const int gid = rgp * 16 + bg;      // 0..127 (reduction group)
    const int r0 = rgp * 2, r1 = r0 + 1;
    const size_t rowg0 = (size_t)((r0 >> 2) * HH + j0 + (r0 & 3));
    const size_t rowg1 = (size_t)((r1 >> 2) * HH + j0 + (r1 & 3));

    // ---- pointwise mapping (first 256 threads); c in register ----
    const int pb = tid & 63, pjj = (tid >> 6) & 3;
    const bool pact = (tid < 256);
    float c_reg = pact ? c0[pb * HH + j0 + pjj] : 0.f;

    const unsigned e0 = ld_acq(&g_flag[bid]);
    __syncthreads();

    for (int t = 0; t < TT; ++t) {
        if (t > 0) {   // wait for all CTAs to publish h(t)
            if (tid < NCTA) {
                const unsigned target = e0 + (unsigned)t;
                while ((int)(ld_acq(&g_flag[tid]) - target) < 0) {}
            }
            __syncthreads();
        }
        const float* hsrc  = g_hT[t & 1];
        const float* pre_t = g_pre + (size_t)t * G4 * BB;

        // prefetch pre (only ks==0 consumes it)
        float4 pr0, pr1;
        if (ks == 0) {
            pr0 = __ldg((const float4*)&pre_t[rowg0 * BB + bg * 4]);
            pr1 = __ldg((const float4*)&pre_t[rowg1 * BB + bg * 4]);
        }

        // ---- stage whole h: linear 128KB copy, coalesced ----
#pragma unroll
        for (int j = 0; j < 16; j++) {
            float4 v = __ldcg((const float4*)hsrc + tid + j * 512);
            *((float4*)hs + tid + j * 512) = v;
        }
        __syncthreads();

        // ---- GEMM: 128 k per thread, FFMA2 ----
        ull a00 = 0ull, a01 = 0ull, a10 = 0ull, a11 = 0ull;
        {
            const float* hb = hs + ks * 128 * 64 + bg * 4;
            const float* wp = wtd + ks * 128 * 32 + rgp * 4;
#pragma unroll 16
            for (int kk = 0; kk < 128; ++kk) {
                ulonglong2 hv = *(const ulonglong2*)(hb + kk * 64);
                ulonglong2 wv = *(const ulonglong2*)(wp + kk * 32);
                a00 = fma2(hv.x, wv.x, a00);   // (b0,b1) x r0
                a01 = fma2(hv.y, wv.x, a01);   // (b2,b3) x r0
                a10 = fma2(hv.x, wv.y, a10);   // (b0,b1) x r1
                a11 = fma2(hv.y, wv.y, a11);   // (b2,b3) x r1
            }
        }

        // ---- k-segment reduction: ks 1..3 publish, ks 0 gathers ----
        if (ks != 0) {
            ull* rp = (ull*)rbuf + ((size_t)gid * 3 + (ks - 1)) * 4;
            rp[0] = a00; rp[1] = a01; rp[2] = a10; rp[3] = a11;
        }
        __syncthreads();
        if (ks == 0) {
#pragma unroll
            for (int p = 0; p < 3; p++) {
                const ull* rp = (const ull*)rbuf + ((size_t)gid * 3 + p) * 4;
                a00 = add2(a00, rp[0]); a01 = add2(a01, rp[1]);
                a10 = add2(a10, rp[2]); a11 = add2(a11, rp[3]);
            }
            float2 f00 = unpack2(a00), f01 = unpack2(a01);
            float2 f10 = unpack2(a10), f11 = unpack2(a11);
            const int bb0 = bg * 4;
            gbuf[(bb0 + 0) * 17 + r0] = f00.x + pr0.x;
            gbuf[(bb0 + 1) * 17 + r0] = f00.y + pr0.y;
            gbuf[(bb0 + 2) * 17 + r0] = f01.x + pr0.z;
            gbuf[(bb0 + 3) * 17 + r0] = f01.y + pr0.w;
            gbuf[(bb0 + 0) * 17 + r1] = f10.x + pr1.x;
            gbuf[(bb0 + 1) * 17 + r1] = f10.y + pr1.y;
            gbuf[(bb0 + 2) * 17 + r1] = f11.x + pr1.z;
            gbuf[(bb0 + 3) * 17 + r1] = f11.y + pr1.w;
        }
        __syncthreads();

        // ---- LSTM pointwise (256 threads), writes h directly to g_hT (coalesced) ----
        if (pact) {
            float xi = gbuf[pb * 17 + pjj];
            float xf = gbuf[pb * 17 + 4 + pjj];
            float xg = gbuf[pb * 17 + 8 + pjj];
            float xo = gbuf[pb * 17 + 12 + pjj];
            float si = 1.0f / (1.0f + __expf(-xi));
            float sf = 1.0f / (1.0f + __expf(-xf));
            float so = 1.0f / (1.0f + __expf(-xo));
            float tg = tanhf(xg);
            c_reg = sf * c_reg + si * tg;
            float hn = so * tanhf(c_reg);
            __stcg(&g_hT[(t + 1) & 1][(j0 + pjj) * BB + pb], hn);
            hres[pjj * 64 + pb] = hn;
        }
        __syncthreads();
        if (tid < 64) {  // h history in [t][b][H] layout for k_out
            float4 hv = make_float4(hres[0 * 64 + tid], hres[1 * 64 + tid],
                                    hres[2 * 64 + tid], hres[3 * 64 + tid]);
            __stcg((float4*)&g_hall[(size_t)t * BB * HH + tid * HH + j0], hv);
        }
        __syncthreads();
        if (tid == 0) st_rel(&g_flag[bid], e0 + (unsigned)(t + 1));
    }
}

// ---------------- kernel 4: out[b][t][a] = h_all[t][b] . W'[b][a] + b_out[a] ----------
__global__ __launch_bounds__(256) void k_out(const float* __restrict__ b_out,
                                             float* __restrict__ out) {
    __shared__ float As[64][68];
    __shared__ float Bs[64][68];
    const int b  = blockIdx.z;
    const int m0 = blockIdx.y * 64;
    const int n0 = blockIdx.x * 64;
    const int tid = threadIdx.x;
    const int tm = tid >> 4, tn = tid & 15;
    float acc[4][4] = {};

    for (int k0 = 0; k0 < HH; k0 += 64) {
#pragma unroll
        for (int i = 0; i < 4; i++) {
            int id = tid + i * 256;
            int r = id >> 4, c4 = (id & 15) << 2;
            *(float4*)&As[r][c4] = *(const float4*)&g_hall[((size_t)(m0 + r) * BB + b) * HH + k0 + c4];
            *(float4*)&Bs[r][c4] = *(const float4*)&g_wp[((size_t)b * AA + n0 + r) * HH + k0 + c4];
        }
        __syncthreads();
#pragma unroll
        for (int k = 0; k < 64; k += 4) {
            float4 a[4], bv[4];
#pragma unroll
            for (int i = 0; i < 4; i++) a[i] = *(const float4*)&As[tm * 4 + i][k];
#pragma unroll
            for (int j = 0; j < 4; j++) bv[j] = *(const float4*)&Bs[tn * 4 + j][k];
#pragma unroll
            for (int i = 0; i < 4; i++)
#pragma unroll
                for (int j = 0; j < 4; j++)
                    acc[i][j] += a[i].x * bv[j].x + a[i].y * bv[j].y + a[i].z * bv[j].z + a[i].w * bv[j].w;
        }
        __syncthreads();
    }
    float4 bo = *(const float4*)&b_out[n0 + tn * 4];
#pragma unroll
    for (int i = 0; i < 4; i++) {
        int m = m0 + tm * 4 + i;
        float4 v = make_float4(acc[i][0] + bo.x, acc[i][1] + bo.y,
                               acc[i][2] + bo.z, acc[i][3] + bo.w);
        *(float4*)&out[((size_t)b * TT + m) * AA + n0 + tn * 4] = v;
    }
}

// ---------------- launch ----------------
extern "C" void kernel_launch(void* const* d_in, const int* in_sizes, int n_in,
                              void* d_out, int out_size) {
    const float* x     = (const float*)d_in[0];
    const float* w_ih  = (const float*)d_in[1];
    const float* w_hh  = (const float*)d_in[2];
    const float* b_ih  = (const float*)d_in[3];
    const float* b_hh  = (const float*)d_in[4];
    const float* Mm    = (const float*)d_in[5];
    const float* w_out = (const float*)d_in[6];
    const float* b_out = (const float*)d_in[7];
    const float* h0    = (const float*)d_in[8];
    const float* c0    = (const float*)d_in[9];
    float* out = (float*)d_out;

    const int loop_smem = (16384 + 32768 + 3072 + 1088 + 256) * sizeof(float);  // ~210 KB
    static int attr_done = 0;
    if (!attr_done) {
        cudaFuncSetAttribute(k_loop, cudaFuncAttributeMaxDynamicSharedMemorySize, loop_smem);
        attr_done = 1;
    }

    k_init<<<128, 256>>>(h0);
    k_pregates<<<dim3(G4 / 64, TT), 256>>>(x, w_ih, b_ih, b_hh);
    k_wprime<<<dim3(HH / 64, AA / 64, BB), 256>>>(w_out, Mm);

    k_loop<<<NCTA, 512, loop_smem>>>(w_hh, c0);

    k_out<<<dim3(AA / 64, TT / 64, BB), 256>>>(b_out, out);
}

// round 6
// speedup vs baseline: 2.1121x; 1.5113x over previous
#include <cuda_runtime.h>
#include <cstdint>
#include <cstddef>

#define BB 64
#define TT 512
#define AA 128
#define HH 512
#define G4 2048  // 4*H
#define NCTA 128

typedef unsigned long long ull;

// ---------------- scratch (static device allocations) ----------------
__device__ float g_pre[(size_t)TT * G4 * BB];   // 256MB: pre-gates [t][row][b]
__device__ float g_hall[(size_t)TT * BB * HH];  // 64MB : h history [t][b][H]
__device__ ull   g_hT2[2][(HH / 2) * BB];       // recurrent h, kpair-packed: [buf][kp*64+b]=(h[2kp][b],h[2kp+1][b])
__device__ float g_wp[(size_t)BB * AA * HH];    // 16MB : W'[b]
__device__ unsigned g_flag[NCTA];               // epoch flags (monotone)

__device__ __forceinline__ void st_rel(unsigned* p, unsigned v) {
    asm volatile("st.release.gpu.global.u32 [%0], %1;" :: "l"(p), "r"(v) : "memory");
}
__device__ __forceinline__ unsigned ld_acq(const unsigned* p) {
    unsigned v;
    asm volatile("ld.acquire.gpu.global.u32 %0, [%1];" : "=r"(v) : "l"(p) : "memory");
    return v;
}
__device__ __forceinline__ ull fma2(ull a, ull b, ull c) {
    ull d;
    asm("fma.rn.f32x2 %0, %1, %2, %3;" : "=l"(d) : "l"(a), "l"(b), "l"(c));
    return d;
}
__device__ __forceinline__ ull add2(ull a, ull b) {
    ull d;
    asm("add.rn.f32x2 %0, %1, %2;" : "=l"(d) : "l"(a), "l"(b));
    return d;
}
__device__ __forceinline__ float2 unpack2(ull v) {
    float lo, hi;
    asm("mov.b64 {%0, %1}, %2;" : "=f"(lo), "=f"(hi) : "l"(v));
    return make_float2(lo, hi);
}

// ---------------- kernel 0: pack h0 into g_hT2[0] ----------------
__global__ void k_init(const float* __restrict__ h0) {
    int id = blockIdx.x * blockDim.x + threadIdx.x;   // 16384 = 256 kp x 64 b
    int kp = id >> 6, b = id & 63;
    float2 v = make_float2(h0[b * HH + 2 * kp], h0[b * HH + 2 * kp + 1]);
    ((float2*)g_hT2[0])[id] = v;
}

// ---------------- kernel 1: pre[t][row][b] (transposed store) ----------------
__global__ __launch_bounds__(256) void k_pregates(const float* __restrict__ x,
                                                  const float* __restrict__ w_ih,
                                                  const float* __restrict__ b_ih,
                                                  const float* __restrict__ b_hh) {
    __shared__ float As[64][68];
    __shared__ float Bs[64][68];
    const int t  = blockIdx.y;
    const int n0 = blockIdx.x * 64;
    const int tid = threadIdx.x;
    const int tm = tid >> 4;
    const int tn = tid & 15;
    float acc[4][4] = {};

    for (int k0 = 0; k0 < AA; k0 += 64) {
#pragma unroll
        for (int i = 0; i < 4; i++) {
            int id = tid + i * 256;
            int r = id >> 4, c4 = (id & 15) << 2;
            *(float4*)&As[r][c4] = *(const float4*)&x[((size_t)r * TT + t) * AA + k0 + c4];
            *(float4*)&Bs[r][c4] = *(const float4*)&w_ih[(size_t)(n0 + r) * AA + k0 + c4];
        }
        __syncthreads();
#pragma unroll
        for (int k = 0; k < 64; k += 4) {
            float4 a[4], b[4];
#pragma unroll
            for (int i = 0; i < 4; i++) a[i] = *(const float4*)&As[tm * 4 + i][k];
#pragma unroll
            for (int j = 0; j < 4; j++) b[j] = *(const float4*)&Bs[tn * 4 + j][k];
#pragma unroll
            for (int i = 0; i < 4; i++)
#pragma unroll
                for (int j = 0; j < 4; j++)
                    acc[i][j] += a[i].x * b[j].x + a[i].y * b[j].y + a[i].z * b[j].z + a[i].w * b[j].w;
        }
        __syncthreads();
    }
    float4 bi = *(const float4*)&b_ih[n0 + tn * 4];
    float4 bh = *(const float4*)&b_hh[n0 + tn * 4];
    float bias[4] = {bi.x + bh.x, bi.y + bh.y, bi.z + bh.z, bi.w + bh.w};
#pragma unroll
    for (int j = 0; j < 4; j++) {
        float4 v = make_float4(acc[0][j] + bias[j], acc[1][j] + bias[j],
                               acc[2][j] + bias[j], acc[3][j] + bias[j]);
        *(float4*)&g_pre[((size_t)t * G4 + n0 + tn * 4 + j) * BB + tm * 4] = v;
    }
}

// ---------------- kernel 2: W'[b] = w_out + w_out @ M[b] ----------------
__global__ __launch_bounds__(256) void k_wprime(const float* __restrict__ w_out,
                                                const float* __restrict__ Mm) {
    __shared__ float As[64][68];
    __shared__ float Bs[64][68];
    const int b  = blockIdx.z;
    const int m0 = blockIdx.y * 64;
    const int n0 = blockIdx.x * 64;
    const int tid = threadIdx.x;
    const int tm = tid >> 4, tn = tid & 15;
    float acc[4][4] = {};

    for (int k0 = 0; k0 < HH; k0 += 64) {
#pragma unroll
        for (int i = 0; i < 4; i++) {
            int id = tid + i * 256;
            int r = id >> 4, c4 = (id & 15) << 2;
            *(float4*)&As[r][c4] = *(const float4*)&w_out[(size_t)(m0 + r) * HH + k0 + c4];
            *(float4*)&Bs[r][c4] = *(const float4*)&Mm[((size_t)b * HH + k0 + r) * HH + n0 + c4];
        }
        __syncthreads();
#pragma unroll
        for (int k = 0; k < 64; k += 4) {
            float4 a[4];
#pragma unroll
            for (int i = 0; i < 4; i++) a[i] = *(const float4*)&As[tm * 4 + i][k];
#pragma unroll
            for (int kk = 0; kk < 4; kk++) {
                float4 bv = *(const float4*)&Bs[k + kk][tn * 4];
#pragma unroll
                for (int i = 0; i < 4; i++) {
                    float av = (kk == 0) ? a[i].x : (kk == 1) ? a[i].y : (kk == 2) ? a[i].z : a[i].w;
                    acc[i][0] += av * bv.x; acc[i][1] += av * bv.y;
                    acc[i][2] += av * bv.z; acc[i][3] += av * bv.w;
                }
            }
        }
        __syncthreads();
    }
#pragma unroll
    for (int i = 0; i < 4; i++) {
        int m = m0 + tm * 4 + i;
        float4 w0 = *(const float4*)&w_out[(size_t)m * HH + n0 + tn * 4];
        float4 v = make_float4(acc[i][0] + w0.x, acc[i][1] + w0.y,
                               acc[i][2] + w0.z, acc[i][3] + w0.w);
        *(float4*)&g_wp[((size_t)b * AA + m) * HH + n0 + tn * 4] = v;
    }
}

// ---------------- kernel 3: persistent recurrent loop (all 512 steps) ----------------
// 128 CTAs = 32 unit-groups x 4 batch-groups. CTA owns 16 hidden units x 16 batches:
// 64 gate rows resident in smem (kpair-packed ull), h staged 32KB/step.
// Warp: lanes = 2 bgroups x 16 rowgroups (h broadcast across rg); 8 warps = 8 k-segments.
// Thread tile 8b x 4r, acc = f32x2 over k-parity. 4 independent barrier domains.
__global__ __launch_bounds__(256) void k_loop(const float* __restrict__ w_hh,
                                              const float* __restrict__ c0) {
    extern __shared__ char smraw[];
    ull*        w2u   = (ull*)smraw;                          // [256 kp][64 r]   131072 B
    ull*        hs2u  = (ull*)(smraw + 131072);               // [256 kp][16 b]   32768 B (union)
    ulonglong2* rbuf2 = (ulonglong2*)(smraw + 131072);        // [8][16][33] u2   67584 B (alias)
    float*      gbuf  = (float*)(smraw + 131072 + 67584);     // [64 r][24]       6144 B
    float*      hres  = (float*)(smraw + 131072 + 67584 + 6144); // [16 b][17]    1088 B

    const int tid = threadIdx.x;
    const int bid = blockIdx.x;
    const int jg  = bid & 31;        // unit group -> units j0..j0+15
    const int bgc = bid >> 5;        // batch group (0..3) -> batches b0..b0+15
    const int j0  = jg * 16;
    const int b0  = bgc * 16;

    // ---- load w rows (kpair-packed): w2u[kp*64 + r], r = gate*16 + ju ----
    {
        const int r = tid >> 2, kq = tid & 3;
        const int gate = r >> 4, ju = r & 15;
        const float* wrow = w_hh + (size_t)(gate * HH + j0 + ju) * HH;
#pragma unroll 8
        for (int i = 0; i < 64; ++i) {
            int kp = kq * 64 + i;
            float2 wv = *(const float2*)(wrow + 2 * kp);
            ull v;
            asm("mov.b64 %0, {%1,%2};" : "=l"(v) : "f"(wv.x), "f"(wv.y));
            w2u[kp * 64 + r] = v;
        }
    }

    // ---- GEMM mapping ----
    const int lane = tid & 31;
    const int ksg  = tid >> 5;       // k segment 0..7 (32 kp each)
    const int bg   = lane & 1;       // batch half (8 b)
    const int rg   = lane >> 1;      // row group (4 rows)

    // ---- finalize mapping: thread owns gate values f0..f0+3 ----
    const int f0    = tid * 4;
    const int fg    = f0 >> 5;                       // group = rg*2+bg
    const int f_row = (fg >> 1) * 4 + ((f0 >> 3) & 3);
    const int f_b   = (fg & 1) * 8 + (f0 & 7);       // f0&7 in {0,4}
    const int f_gate = f_row >> 4, f_ju = f_row & 15;
    const float* preptr = g_pre + (size_t)(f_gate * HH + j0 + f_ju) * BB + b0 + f_b;

    // ---- pointwise mapping; c lives in a register all 512 steps ----
    const int pb = tid & 15, pu = tid >> 4;
    float c_reg = c0[(size_t)(b0 + pb) * HH + j0 + pu];
    const int hT_off = ((j0 + pu) >> 1) * 128 + (b0 + pb) * 2 + ((j0 + pu) & 1);

    const unsigned e0 = ld_acq(&g_flag[bid]);
    __syncthreads();

    for (int t = 0; t < TT; ++t) {
        if (t > 0) {   // wait for the 32 CTAs of this batch domain
            if (tid < 32) {
                const unsigned target = e0 + (unsigned)t;
                const unsigned* fp = &g_flag[bgc * 32 + tid];
                while ((int)(ld_acq(fp) - target) < 0) {}
            }
            __syncthreads();
        }
        const ulonglong2* hsrc = (const ulonglong2*)g_hT2[t & 1];

        // prefetch pre (static data; hidden behind GEMM)
        float4 pr = __ldg((const float4*)(preptr + (size_t)t * G4 * BB));

        // ---- stage h slice (32 KB): 8x LDG.128 -> STS.128, coalesced ----
        {
            ulonglong2 v[8];
#pragma unroll
            for (int i = 0; i < 8; ++i) {
                int idx2 = tid + i * 256;                 // 0..2047
                int kp = idx2 >> 3, blp = idx2 & 7;
                v[i] = __ldcg(hsrc + kp * 32 + (b0 >> 1) + blp);
            }
#pragma unroll
            for (int i = 0; i < 8; ++i) {
                int idx2 = tid + i * 256;
                int kp = idx2 >> 3, blp = idx2 & 7;
                *(ulonglong2*)(hs2u + kp * 16 + blp * 2) = v[i];
            }
        }
        __syncthreads();

        // ---- GEMM: 32 kp per thread, 32 fma2 per kp ----
        ull acc[4][8];
#pragma unroll
        for (int r = 0; r < 4; r++)
#pragma unroll
            for (int b = 0; b < 8; b++) acc[r][b] = 0ull;
        {
            const ull* hp = hs2u + (ksg * 32) * 16 + bg * 8;
            const ull* wp = w2u + (size_t)(ksg * 32) * 64 + rg * 4;
#pragma unroll 2
            for (int kp = 0; kp < 32; ++kp) {
                ulonglong2 h01 = *(const ulonglong2*)(hp + kp * 16);
                ulonglong2 h23 = *(const ulonglong2*)(hp + kp * 16 + 2);
                ulonglong2 h45 = *(const ulonglong2*)(hp + kp * 16 + 4);
                ulonglong2 h67 = *(const ulonglong2*)(hp + kp * 16 + 6);
                ulonglong2 w01 = *(const ulonglong2*)(wp + kp * 64);
                ulonglong2 w23 = *(const ulonglong2*)(wp + kp * 64 + 2);
                ull hv[8] = {h01.x, h01.y, h23.x, h23.y, h45.x, h45.y, h67.x, h67.y};
                ull wv[4] = {w01.x, w01.y, w23.x, w23.y};
#pragma unroll
                for (int r = 0; r < 4; r++)
#pragma unroll
                    for (int b = 0; b < 8; b++)
                        acc[r][b] = fma2(hv[b], wv[r], acc[r][b]);
            }
        }
        __syncthreads();   // hs2u dead -> rbuf alias safe

        // ---- publish partials: rbuf2[ksg][apair][lane] (conflict-free STS.128) ----
        {
            ulonglong2* rp = rbuf2 + ksg * 528 + lane;
#pragma unroll
            for (int r = 0; r < 4; r++)
#pragma unroll
                for (int b = 0; b < 8; b += 2)
                    rp[((r * 8 + b) >> 1) * 33] = make_ulonglong2(acc[r][b], acc[r][b + 1]);
        }
        __syncthreads();

        // ---- finalize 4 gate values: sum 8 segments, collapse k-parity, add pre ----
        {
            const int ap0 = (f0 & 31) >> 1;   // first of two consecutive apairs
            ulonglong2 s01 = rbuf2[ap0 * 33 + fg];
            ulonglong2 s23 = rbuf2[(ap0 + 1) * 33 + fg];
            ull s0 = s01.x, s1 = s01.y, s2 = s23.x, s3 = s23.y;
#pragma unroll
            for (int ks = 1; ks < 8; ++ks) {
                ulonglong2 a01 = rbuf2[ks * 528 + ap0 * 33 + fg];
                ulonglong2 a23 = rbuf2[ks * 528 + (ap0 + 1) * 33 + fg];
                s0 = add2(s0, a01.x); s1 = add2(s1, a01.y);
                s2 = add2(s2, a23.x); s3 = add2(s3, a23.y);
            }
            float2 u0 = unpack2(s0), u1 = unpack2(s1), u2 = unpack2(s2), u3 = unpack2(s3);
            float4 g = make_float4(u0.x + u0.y + pr.x, u1.x + u1.y + pr.y,
                                   u2.x + u2.y + pr.z, u3.x + u3.y + pr.w);
            *(float4*)(gbuf + f_row * 24 + f_b) = g;
        }
        __syncthreads();

        // ---- LSTM pointwise; h handoff to g_hT2 (kpair layout, coalesced) ----
        {
            float xi = gbuf[(0 * 16 + pu) * 24 + pb];
            float xf = gbuf[(1 * 16 + pu) * 24 + pb];
            float xg = gbuf[(2 * 16 + pu) * 24 + pb];
            float xo = gbuf[(3 * 16 + pu) * 24 + pb];
            float si = 1.0f / (1.0f + __expf(-xi));
            float sf = 1.0f / (1.0f + __expf(-xf));
            float so = 1.0f / (1.0f + __expf(-xo));
            float tg = tanhf(xg);
            c_reg = sf * c_reg + si * tg;
            float hn = so * tanhf(c_reg);
            __stcg((float*)g_hT2[(t + 1) & 1] + hT_off, hn);
            hres[pb * 17 + pu] = hn;
        }
        __syncthreads();

        // ---- h history for k_out: [t][b][H], 64B-contiguous per 16 lanes ----
        {
            int bl = tid >> 4, jl = tid & 15;
            __stcg(&g_hall[(size_t)t * BB * HH + (size_t)(b0 + bl) * HH + j0 + jl],
                   hres[bl * 17 + jl]);
        }

        if (tid == 0) st_rel(&g_flag[bid], e0 + (unsigned)(t + 1));
    }
}

// ---------------- kernel 4: out[b][t][a] = h_all[t][b] . W'[b][a] + b_out[a] ----------
__global__ __launch_bounds__(256) void k_out(const float* __restrict__ b_out,
                                             float* __restrict__ out) {
    __shared__ float As[64][68];
    __shared__ float Bs[64][68];
    const int b  = blockIdx.z;
    const int m0 = blockIdx.y * 64;
    const int n0 = blockIdx.x * 64;
    const int tid = threadIdx.x;
    const int tm = tid >> 4, tn = tid & 15;
    float acc[4][4] = {};

    for (int k0 = 0; k0 < HH; k0 += 64) {
#pragma unroll
        for (int i = 0; i < 4; i++) {
            int id = tid + i * 256;
            int r = id >> 4, c4 = (id & 15) << 2;
            *(float4*)&As[r][c4] = *(const float4*)&g_hall[((size_t)(m0 + r) * BB + b) * HH + k0 + c4];
            *(float4*)&Bs[r][c4] = *(const float4*)&g_wp[((size_t)b * AA + n0 + r) * HH + k0 + c4];
        }
        __syncthreads();
#pragma unroll
        for (int k = 0; k < 64; k += 4) {
            float4 a[4], bv[4];
#pragma unroll
            for (int i = 0; i < 4; i++) a[i] = *(const float4*)&As[tm * 4 + i][k];
#pragma unroll
            for (int j = 0; j < 4; j++) bv[j] = *(const float4*)&Bs[tn * 4 + j][k];
#pragma unroll
            for (int i = 0; i < 4; i++)
#pragma unroll
                for (int j = 0; j < 4; j++)
                    acc[i][j] += a[i].x * bv[j].x + a[i].y * bv[j].y + a[i].z * bv[j].z + a[i].w * bv[j].w;
        }
        __syncthreads();
    }
    float4 bo = *(const float4*)&b_out[n0 + tn * 4];
#pragma unroll
    for (int i = 0; i < 4; i++) {
        int m = m0 + tm * 4 + i;
        float4 v = make_float4(acc[i][0] + bo.x, acc[i][1] + bo.y,
                               acc[i][2] + bo.z, acc[i][3] + bo.w);
        *(float4*)&out[((size_t)b * TT + m) * AA + n0 + tn * 4] = v;
    }
}

// ---------------- launch ----------------
extern "C" void kernel_launch(void* const* d_in, const int* in_sizes, int n_in,
                              void* d_out, int out_size) {
    const float* x     = (const float*)d_in[0];
    const float* w_ih  = (const float*)d_in[1];
    const float* w_hh  = (const float*)d_in[2];
    const float* b_ih  = (const float*)d_in[3];
    const float* b_hh  = (const float*)d_in[4];
    const float* Mm    = (const float*)d_in[5];
    const float* w_out = (const float*)d_in[6];
    const float* b_out = (const float*)d_in[7];
    const float* h0    = (const float*)d_in[8];
    const float* c0    = (const float*)d_in[9];
    float* out = (float*)d_out;

    const int loop_smem = 131072 + 67584 + 6144 + 1088;  // 205888 B
    static int attr_done = 0;
    if (!attr_done) {
        cudaFuncSetAttribute(k_loop, cudaFuncAttributeMaxDynamicSharedMemorySize, loop_smem);
        attr_done = 1;
    }

    k_init<<<64, 256>>>(h0);
    k_pregates<<<dim3(G4 / 64, TT), 256>>>(x, w_ih, b_ih, b_hh);
    k_wprime<<<dim3(HH / 64, AA / 64, BB), 256>>>(w_out, Mm);

    k_loop<<<NCTA, 256, loop_smem>>>(w_hh, c0);

    k_out<<<dim3(AA / 64, TT / 64, BB), 256>>>(b_out, out);
}

// round 7
// speedup vs baseline: 2.2410x; 1.0610x over previous
#include <cuda_runtime.h>
#include <cstdint>
#include <cstddef>

#define BB 64
#define TT 512
#define AA 128
#define HH 512
#define G4 2048  // 4*H
#define NCTA 128

typedef unsigned long long ull;

// ---------------- scratch (static device allocations) ----------------
__device__ float g_pre[(size_t)TT * G4 * BB];   // 256MB: pre-gates [t][row][b]
__device__ float g_hall[(size_t)TT * BB * HH];  // 64MB : h history [t][b][H]
__device__ ull   g_hT2[2][(HH / 2) * BB];       // recurrent h, kpair-packed: [buf][kp*64+b] = (h[2kp][b], h[2kp+1][b])
__device__ float g_wp[(size_t)BB * AA * HH];    // 16MB : W'[b]
__device__ unsigned g_flag[NCTA];               // epoch flags (monotone)

__device__ __forceinline__ void st_rel(unsigned* p, unsigned v) {
    asm volatile("st.release.gpu.global.u32 [%0], %1;" :: "l"(p), "r"(v) : "memory");
}
__device__ __forceinline__ unsigned ld_acq(const unsigned* p) {
    unsigned v;
    asm volatile("ld.acquire.gpu.global.u32 %0, [%1];" : "=r"(v) : "l"(p) : "memory");
    return v;
}
__device__ __forceinline__ ull fma2(ull a, ull b, ull c) {
    ull d;
    asm("fma.rn.f32x2 %0, %1, %2, %3;" : "=l"(d) : "l"(a), "l"(b), "l"(c));
    return d;
}
__device__ __forceinline__ ull add2(ull a, ull b) {
    ull d;
    asm("add.rn.f32x2 %0, %1, %2;" : "=l"(d) : "l"(a), "l"(b));
    return d;
}
__device__ __forceinline__ float2 unpack2(ull v) {
    float lo, hi;
    asm("mov.b64 {%0, %1}, %2;" : "=f"(lo), "=f"(hi) : "l"(v));
    return make_float2(lo, hi);
}

// ---------------- kernel 0: pack h0 into g_hT2[0] ----------------
__global__ void k_init(const float* __restrict__ h0) {
    int id = blockIdx.x * blockDim.x + threadIdx.x;   // 16384 = 256 kp x 64 b
    int kp = id >> 6, b = id & 63;
    float2 v = make_float2(h0[b * HH + 2 * kp], h0[b * HH + 2 * kp + 1]);
    ((float2*)g_hT2[0])[id] = v;
}

// ---------------- kernel 1: pre[t][row][b] (transposed store, f32x2) ----------------
__global__ __launch_bounds__(256) void k_pregates(const float* __restrict__ x,
                                                  const float* __restrict__ w_ih,
                                                  const float* __restrict__ b_ih,
                                                  const float* __restrict__ b_hh) {
    __shared__ float As[64][68];
    __shared__ float Bs[64][68];
    const int t  = blockIdx.y;
    const int n0 = blockIdx.x * 64;
    const int tid = threadIdx.x;
    const int tm = tid >> 4;
    const int tn = tid & 15;
    ull acc2[4][4] = {};

    for (int k0 = 0; k0 < AA; k0 += 64) {
#pragma unroll
        for (int i = 0; i < 4; i++) {
            int id = tid + i * 256;
            int r = id >> 4, c4 = (id & 15) << 2;
            *(float4*)&As[r][c4] = *(const float4*)&x[((size_t)r * TT + t) * AA + k0 + c4];
            *(float4*)&Bs[r][c4] = *(const float4*)&w_ih[(size_t)(n0 + r) * AA + k0 + c4];
        }
        __syncthreads();
#pragma unroll
        for (int k = 0; k < 64; k += 4) {
            ulonglong2 a[4], b[4];
#pragma unroll
            for (int i = 0; i < 4; i++) a[i] = *(const ulonglong2*)&As[tm * 4 + i][k];
#pragma unroll
            for (int j = 0; j < 4; j++) b[j] = *(const ulonglong2*)&Bs[tn * 4 + j][k];
#pragma unroll
            for (int i = 0; i < 4; i++)
#pragma unroll
                for (int j = 0; j < 4; j++) {
                    acc2[i][j] = fma2(a[i].x, b[j].x, acc2[i][j]);
                    acc2[i][j] = fma2(a[i].y, b[j].y, acc2[i][j]);
                }
        }
        __syncthreads();
    }
    float4 bi = *(const float4*)&b_ih[n0 + tn * 4];
    float4 bh = *(const float4*)&b_hh[n0 + tn * 4];
    float bias[4] = {bi.x + bh.x, bi.y + bh.y, bi.z + bh.z, bi.w + bh.w};
#pragma unroll
    for (int j = 0; j < 4; j++) {
        float r[4];
#pragma unroll
        for (int i = 0; i < 4; i++) {
            float2 u = unpack2(acc2[i][j]);
            r[i] = u.x + u.y + bias[j];
        }
        *(float4*)&g_pre[((size_t)t * G4 + n0 + tn * 4 + j) * BB + tm * 4] =
            make_float4(r[0], r[1], r[2], r[3]);
    }
}

// ---------------- kernel 2: W'[b] = w_out + w_out @ M[b] ----------------
__global__ __launch_bounds__(256) void k_wprime(const float* __restrict__ w_out,
                                                const float* __restrict__ Mm) {
    __shared__ float As[64][68];
    __shared__ float Bs[64][68];
    const int b  = blockIdx.z;
    const int m0 = blockIdx.y * 64;
    const int n0 = blockIdx.x * 64;
    const int tid = threadIdx.x;
    const int tm = tid >> 4, tn = tid & 15;
    float acc[4][4] = {};

    for (int k0 = 0; k0 < HH; k0 += 64) {
#pragma unroll
        for (int i = 0; i < 4; i++) {
            int id = tid + i * 256;
            int r = id >> 4, c4 = (id & 15) << 2;
            *(float4*)&As[r][c4] = *(const float4*)&w_out[(size_t)(m0 + r) * HH + k0 + c4];
            *(float4*)&Bs[r][c4] = *(const float4*)&Mm[((size_t)b * HH + k0 + r) * HH + n0 + c4];
        }
        __syncthreads();
#pragma unroll
        for (int k = 0; k < 64; k += 4) {
            float4 a[4];
#pragma unroll
            for (int i = 0; i < 4; i++) a[i] = *(const float4*)&As[tm * 4 + i][k];
#pragma unroll
            for (int kk = 0; kk < 4; kk++) {
                float4 bv = *(const float4*)&Bs[k + kk][tn * 4];
#pragma unroll
                for (int i = 0; i < 4; i++) {
                    float av = (kk == 0) ? a[i].x : (kk == 1) ? a[i].y : (kk == 2) ? a[i].z : a[i].w;
                    acc[i][0] += av * bv.x; acc[i][1] += av * bv.y;
                    acc[i][2] += av * bv.z; acc[i][3] += av * bv.w;
                }
            }
        }
        __syncthreads();
    }
#pragma unroll
    for (int i = 0; i < 4; i++) {
        int m = m0 + tm * 4 + i;
        float4 w0 = *(const float4*)&w_out[(size_t)m * HH + n0 + tn * 4];
        float4 v = make_float4(acc[i][0] + w0.x, acc[i][1] + w0.y,
                               acc[i][2] + w0.z, acc[i][3] + w0.w);
        *(float4*)&g_wp[((size_t)b * AA + m) * HH + n0 + tn * 4] = v;
    }
}

// ---------------- kernel 3: persistent recurrent loop (all 512 steps) ----------------
// 128 CTAs = 32 unit-groups x 4 batch-groups; 512 threads (16 warps).
// CTA: 16 units x 16 batches, 64 gate rows resident in smem (kpair-packed).
// Warps: 8 k-segments x 2 batch-halves. Thread tile 4r x 4b, f32x2 over k-parity.
// Publish partials rbuf2[j][tid] (contiguous STS.128); merged finalize+pointwise.
__global__ __launch_bounds__(512) void k_loop(const float* __restrict__ w_hh,
                                              const float* __restrict__ c0) {
    extern __shared__ char smraw[];
    ull*        w2u   = (ull*)smraw;                   // [256 kp][64 r]  131072 B
    ull*        hs2u  = (ull*)(smraw + 131072);        // [256 kp][16 b]  32768 B (alias)
    ulonglong2* rbuf2 = (ulonglong2*)(smraw + 131072); // [8 j][512 tid]  65536 B (alias)
    ull*        rbufU = (ull*)(smraw + 131072);

    const int tid = threadIdx.x;
    const int bid = blockIdx.x;
    const int jg  = bid & 31;        // unit group -> units j0..j0+15
    const int bgc = bid >> 5;        // batch group -> batches b0..b0+15
    const int j0  = jg * 16;
    const int b0  = bgc * 16;

    // ---- load w rows (kpair-packed): w2u[kp*64 + r], r = gate*16 + ju ----
    {
        const int r = tid >> 3, kq = tid & 7;
        const int gate = r >> 4, ju = r & 15;
        const float* wrow = w_hh + (size_t)(gate * HH + j0 + ju) * HH;
#pragma unroll 4
        for (int i = 0; i < 32; ++i) {
            int kp = kq * 32 + i;
            float2 wv = *(const float2*)(wrow + 2 * kp);
            ull v;
            asm("mov.b64 %0, {%1,%2};" : "=l"(v) : "f"(wv.x), "f"(wv.y));
            w2u[kp * 64 + r] = v;
        }
    }

    // ---- GEMM mapping: warp = ksg*2 + bh; lane = rg*2 + bg ----
    const int lane = tid & 31;
    const int warp = tid >> 5;
    const int ksg  = warp >> 1;      // 0..7 (32 kp each)
    const int bh   = warp & 1;       // batch half (8 b)
    const int bg   = lane & 1;       // 4-batch group within half
    const int rg   = lane >> 1;      // row group (4 rows)

    // ---- finalize+pointwise mapping (tid < 256): thread owns (pb, pu) ----
    const int pb = tid & 15, pu = tid >> 4;   // valid for tid<256
    const bool pact = (tid < 256);
    float c_reg = 0.f;
    if (pact) c_reg = c0[(size_t)(b0 + pb) * HH + j0 + pu];
    const int hT_off = ((j0 + pu) >> 1) * 128 + (b0 + pb) * 2 + ((j0 + pu) & 1);
    // partial lookup constants for (pb)
    const int fin_bh  = pb >> 3;
    const int fin_bgq = (pb >> 2) & 1;
    const int fin_bp  = (pb >> 1) & 1;
    const int fin_par = pb & 1;

    const unsigned e0 = ld_acq(&g_flag[bid]);
    __syncthreads();

    for (int t = 0; t < TT; ++t) {
        if (t > 0) {   // wait for the 32 CTAs of this batch domain
            if (tid < 32) {
                const unsigned target = e0 + (unsigned)t;
                const unsigned* fp = &g_flag[bgc * 32 + tid];
                while ((int)(ld_acq(fp) - target) < 0) {}
            }
            __syncthreads();
        }
        const ulonglong2* hsrc = (const ulonglong2*)g_hT2[t & 1];

        // prefetch pre for this thread's 4 gates (hidden behind GEMM)
        float pr[4];
        if (pact) {
#pragma unroll
            for (int g = 0; g < 4; g++)
                pr[g] = __ldg(&g_pre[((size_t)t * G4 + g * HH + j0 + pu) * BB + b0 + pb]);
        }

        // ---- stage h slice (32 KB): 4x LDG.128 -> STS.128, coalesced ----
        {
            ulonglong2 v[4];
#pragma unroll
            for (int i = 0; i < 4; ++i) {
                int idx2 = tid + i * 512;                 // 0..2047
                int kp = idx2 >> 3, blp = idx2 & 7;
                v[i] = __ldcg(hsrc + kp * 32 + bgc * 8 + blp);
            }
#pragma unroll
            for (int i = 0; i < 4; ++i) {
                int idx2 = tid + i * 512;
                int kp = idx2 >> 3, blp = idx2 & 7;
                *(ulonglong2*)(hs2u + kp * 16 + blp * 2) = v[i];
            }
        }
        __syncthreads();

        // ---- GEMM: 32 kp per thread, 16 fma2 per kp ----
        ull acc[4][4];
#pragma unroll
        for (int r = 0; r < 4; r++)
#pragma unroll
            for (int b = 0; b < 4; b++) acc[r][b] = 0ull;
        {
            const ull* hp = hs2u + (ksg * 32) * 16 + bh * 8 + bg * 4;
            const ull* wp = w2u + (size_t)(ksg * 32) * 64 + rg * 4;
#pragma unroll 4
            for (int kp = 0; kp < 32; ++kp) {
                ulonglong2 h01 = *(const ulonglong2*)(hp + kp * 16);
                ulonglong2 h23 = *(const ulonglong2*)(hp + kp * 16 + 2);
                ulonglong2 w01 = *(const ulonglong2*)(wp + kp * 64);
                ulonglong2 w23 = *(const ulonglong2*)(wp + kp * 64 + 2);
                ull hv[4] = {h01.x, h01.y, h23.x, h23.y};
                ull wv[4] = {w01.x, w01.y, w23.x, w23.y};
#pragma unroll
                for (int r = 0; r < 4; r++)
#pragma unroll
                    for (int b = 0; b < 4; b++)
                        acc[r][b] = fma2(hv[b], wv[r], acc[r][b]);
            }
        }
        __syncthreads();   // hs2u dead -> rbuf alias safe

        // ---- publish partials: rbuf2[j][tid], j = r'*2 + (b'>>1) ----
        {
            ulonglong2* rp = rbuf2 + tid;
#pragma unroll
            for (int r = 0; r < 4; r++)
#pragma unroll
                for (int bp = 0; bp < 2; bp++)
                    rp[(r * 2 + bp) * 512] = make_ulonglong2(acc[r][bp * 2], acc[r][bp * 2 + 1]);
        }
        __syncthreads();

        // ---- merged finalize + LSTM pointwise (tid < 256) ----
        if (pact) {
            float gv[4];
#pragma unroll
            for (int g = 0; g < 4; g++) {
                const int row = g * 16 + pu;
                const int rgp = row >> 2, rp = row & 3;
                const int j   = rp * 2 + fin_bp;
                const int lofs = (rgp * 2 + fin_bgq) * 2 + fin_par;
                const ull* base = rbufU + (size_t)j * 1024 + fin_bh * 64 + lofs;
                ull s = base[0];
#pragma unroll
                for (int ks = 1; ks < 8; ++ks)
                    s = add2(s, base[ks * 128]);
                float2 u = unpack2(s);
                gv[g] = u.x + u.y + pr[g];
            }
            float si = 1.0f / (1.0f + __expf(-gv[0]));
            float sf = 1.0f / (1.0f + __expf(-gv[1]));
            float tg = tanhf(gv[2]);
            float so = 1.0f / (1.0f + __expf(-gv[3]));
            c_reg = sf * c_reg + si * tg;
            float hn = so * tanhf(c_reg);
            __stcg((float*)g_hT2[(t + 1) & 1] + hT_off, hn);
            __stcg(&g_hall[(size_t)t * BB * HH + (size_t)(b0 + pb) * HH + j0 + pu], hn);
        }
        __syncthreads();
        if (tid == 0) st_rel(&g_flag[bid], e0 + (unsigned)(t + 1));
    }
}

// ---------------- kernel 4: out[b][t][a] = h_all[t][b] . W'[b][a] + b_out[a] (f32x2) ----
__global__ __launch_bounds__(256) void k_out(const float* __restrict__ b_out,
                                             float* __restrict__ out) {
    __shared__ float As[64][68];
    __shared__ float Bs[64][68];
    const int b  = blockIdx.z;
    const int m0 = blockIdx.y * 64;
    const int n0 = blockIdx.x * 64;
    const int tid = threadIdx.x;
    const int tm = tid >> 4, tn = tid & 15;
    ull acc2[4][4] = {};

    for (int k0 = 0; k0 < HH; k0 += 64) {
#pragma unroll
        for (int i = 0; i < 4; i++) {
            int id = tid + i * 256;
            int r = id >> 4, c4 = (id & 15) << 2;
            *(float4*)&As[r][c4] = *(const float4*)&g_hall[((size_t)(m0 + r) * BB + b) * HH + k0 + c4];
            *(float4*)&Bs[r][c4] = *(const float4*)&g_wp[((size_t)b * AA + n0 + r) * HH + k0 + c4];
        }
        __syncthreads();
#pragma unroll
        for (int k = 0; k < 64; k += 4) {
            ulonglong2 a[4], bv[4];
#pragma unroll
            for (int i = 0; i < 4; i++) a[i] = *(const ulonglong2*)&As[tm * 4 + i][k];
#pragma unroll
            for (int j = 0; j < 4; j++) bv[j] = *(const ulonglong2*)&Bs[tn * 4 + j][k];
#pragma unroll
            for (int i = 0; i < 4; i++)
#pragma unroll
                for (int j = 0; j < 4; j++) {
                    acc2[i][j] = fma2(a[i].x, bv[j].x, acc2[i][j]);
                    acc2[i][j] = fma2(a[i].y, bv[j].y, acc2[i][j]);
                }
        }
        __syncthreads();
    }
    float4 bo = *(const float4*)&b_out[n0 + tn * 4];
    float bb[4] = {bo.x, bo.y, bo.z, bo.w};
#pragma unroll
    for (int i = 0; i < 4; i++) {
        float r[4];
#pragma unroll
        for (int j = 0; j < 4; j++) {
            float2 u = unpack2(acc2[i][j]);
            r[j] = u.x + u.y + bb[j];
        }
        int m = m0 + tm * 4 + i;
        *(float4*)&out[((size_t)b * TT + m) * AA + n0 + tn * 4] =
            make_float4(r[0], r[1], r[2], r[3]);
    }
}

// ---------------- launch ----------------
extern "C" void kernel_launch(void* const* d_in, const int* in_sizes, int n_in,
                              void* d_out, int out_size) {
    const float* x     = (const float*)d_in[0];
    const float* w_ih  = (const float*)d_in[1];
    const float* w_hh  = (const float*)d_in[2];
    const float* b_ih  = (const float*)d_in[3];
    const float* b_hh  = (const float*)d_in[4];
    const float* Mm    = (const float*)d_in[5];
    const float* w_out = (const float*)d_in[6];
    const float* b_out = (const float*)d_in[7];
    const float* h0    = (const float*)d_in[8];
    const float* c0    = (const float*)d_in[9];
    float* out = (float*)d_out;

    const int loop_smem = 131072 + 65536;  // 196608 B
    static int attr_done = 0;
    if (!attr_done) {
        cudaFuncSetAttribute(k_loop, cudaFuncAttributeMaxDynamicSharedMemorySize, loop_smem);
        attr_done = 1;
    }

    k_init<<<64, 256>>>(h0);
    k_pregates<<<dim3(G4 / 64, TT), 256>>>(x, w_ih, b_ih, b_hh);
    k_wprime<<<dim3(HH / 64, AA / 64, BB), 256>>>(w_out, Mm);

    k_loop<<<NCTA, 512, loop_smem>>>(w_hh, c0);

    k_out<<<dim3(AA / 64, TT / 64, BB), 256>>>(b_out, out);
}

// round 8
// speedup vs baseline: 2.5862x; 1.1540x over previous
#include <cuda_runtime.h>
#include <cstdint>
#include <cstddef>

#define BB 64
#define TT 512
#define AA 128
#define HH 512
#define G4 2048  // 4*H
#define NCTA 128

typedef unsigned long long ull;

// ---------------- scratch (static device allocations) ----------------
__device__ float g_pre[(size_t)TT * G4 * BB];   // 256MB: pre-gates [t][row][b]
__device__ float g_hall[(size_t)TT * BB * HH];  // 64MB : h history [t][b][H]
__device__ ull   g_hT2[2][(HH / 2) * BB];       // recurrent h, kpair-packed: [buf][kp*64+b]
__device__ float g_wp[(size_t)BB * AA * HH];    // 16MB : W'[b]
__device__ unsigned g_flag[NCTA];               // epoch flags (monotone)

__device__ __forceinline__ void st_rel(unsigned* p, unsigned v) {
    asm volatile("st.release.gpu.global.u32 [%0], %1;" :: "l"(p), "r"(v) : "memory");
}
__device__ __forceinline__ unsigned ld_acq(const unsigned* p) {
    unsigned v;
    asm volatile("ld.acquire.gpu.global.u32 %0, [%1];" : "=r"(v) : "l"(p) : "memory");
    return v;
}
__device__ __forceinline__ ull fma2(ull a, ull b, ull c) {
    ull d;
    asm("fma.rn.f32x2 %0, %1, %2, %3;" : "=l"(d) : "l"(a), "l"(b), "l"(c));
    return d;
}
__device__ __forceinline__ ull add2(ull a, ull b) {
    ull d;
    asm("add.rn.f32x2 %0, %1, %2;" : "=l"(d) : "l"(a), "l"(b));
    return d;
}
__device__ __forceinline__ float2 unpack2(ull v) {
    float lo, hi;
    asm("mov.b64 {%0, %1}, %2;" : "=f"(lo), "=f"(hi) : "l"(v));
    return make_float2(lo, hi);
}
__device__ __forceinline__ float fsigmoid(float x) {
    return __fdividef(1.0f, 1.0f + __expf(-x));
}
__device__ __forceinline__ float ftanh(float x) {
    return __fdividef(2.0f, 1.0f + __expf(-2.0f * x)) - 1.0f;
}

// ---------------- kernel 0: pack h0 into g_hT2[0] ----------------
__global__ void k_init(const float* __restrict__ h0) {
    int id = blockIdx.x * blockDim.x + threadIdx.x;   // 16384 = 256 kp x 64 b
    int kp = id >> 6, b = id & 63;
    float2 v = make_float2(h0[b * HH + 2 * kp], h0[b * HH + 2 * kp + 1]);
    ((float2*)g_hT2[0])[id] = v;
}

// ---------------- kernel 1: pre[t][row][b] (transposed store, f32x2) ----------------
__global__ __launch_bounds__(256) void k_pregates(const float* __restrict__ x,
                                                  const float* __restrict__ w_ih,
                                                  const float* __restrict__ b_ih,
                                                  const float* __restrict__ b_hh) {
    __shared__ float As[64][68];
    __shared__ float Bs[64][68];
    const int t  = blockIdx.y;
    const int n0 = blockIdx.x * 64;
    const int tid = threadIdx.x;
    const int tm = tid >> 4;
    const int tn = tid & 15;
    ull acc2[4][4] = {};

    for (int k0 = 0; k0 < AA; k0 += 64) {
#pragma unroll
        for (int i = 0; i < 4; i++) {
            int id = tid + i * 256;
            int r = id >> 4, c4 = (id & 15) << 2;
            *(float4*)&As[r][c4] = *(const float4*)&x[((size_t)r * TT + t) * AA + k0 + c4];
            *(float4*)&Bs[r][c4] = *(const float4*)&w_ih[(size_t)(n0 + r) * AA + k0 + c4];
        }
        __syncthreads();
#pragma unroll
        for (int k = 0; k < 64; k += 4) {
            ulonglong2 a[4], b[4];
#pragma unroll
            for (int i = 0; i < 4; i++) a[i] = *(const ulonglong2*)&As[tm * 4 + i][k];
#pragma unroll
            for (int j = 0; j < 4; j++) b[j] = *(const ulonglong2*)&Bs[tn * 4 + j][k];
#pragma unroll
            for (int i = 0; i < 4; i++)
#pragma unroll
                for (int j = 0; j < 4; j++) {
                    acc2[i][j] = fma2(a[i].x, b[j].x, acc2[i][j]);
                    acc2[i][j] = fma2(a[i].y, b[j].y, acc2[i][j]);
                }
        }
        __syncthreads();
    }
    float4 bi = *(const float4*)&b_ih[n0 + tn * 4];
    float4 bh = *(const float4*)&b_hh[n0 + tn * 4];
    float bias[4] = {bi.x + bh.x, bi.y + bh.y, bi.z + bh.z, bi.w + bh.w};
#pragma unroll
    for (int j = 0; j < 4; j++) {
        float r[4];
#pragma unroll
        for (int i = 0; i < 4; i++) {
            float2 u = unpack2(acc2[i][j]);
            r[i] = u.x + u.y + bias[j];
        }
        *(float4*)&g_pre[((size_t)t * G4 + n0 + tn * 4 + j) * BB + tm * 4] =
            make_float4(r[0], r[1], r[2], r[3]);
    }
}

// ---------------- kernel 2: W'[b] = w_out + w_out @ M[b] ----------------
__global__ __launch_bounds__(256) void k_wprime(const float* __restrict__ w_out,
                                                const float* __restrict__ Mm) {
    __shared__ float As[64][68];
    __shared__ float Bs[64][68];
    const int b  = blockIdx.z;
    const int m0 = blockIdx.y * 64;
    const int n0 = blockIdx.x * 64;
    const int tid = threadIdx.x;
    const int tm = tid >> 4, tn = tid & 15;
    float acc[4][4] = {};

    for (int k0 = 0; k0 < HH; k0 += 64) {
#pragma unroll
        for (int i = 0; i < 4; i++) {
            int id = tid + i * 256;
            int r = id >> 4, c4 = (id & 15) << 2;
            *(float4*)&As[r][c4] = *(const float4*)&w_out[(size_t)(m0 + r) * HH + k0 + c4];
            *(float4*)&Bs[r][c4] = *(const float4*)&Mm[((size_t)b * HH + k0 + r) * HH + n0 + c4];
        }
        __syncthreads();
#pragma unroll
        for (int k = 0; k < 64; k += 4) {
            float4 a[4];
#pragma unroll
            for (int i = 0; i < 4; i++) a[i] = *(const float4*)&As[tm * 4 + i][k];
#pragma unroll
            for (int kk = 0; kk < 4; kk++) {
                float4 bv = *(const float4*)&Bs[k + kk][tn * 4];
#pragma unroll
                for (int i = 0; i < 4; i++) {
                    float av = (kk == 0) ? a[i].x : (kk == 1) ? a[i].y : (kk == 2) ? a[i].z : a[i].w;
                    acc[i][0] += av * bv.x; acc[i][1] += av * bv.y;
                    acc[i][2] += av * bv.z; acc[i][3] += av * bv.w;
                }
            }
        }
        __syncthreads();
    }
#pragma unroll
    for (int i = 0; i < 4; i++) {
        int m = m0 + tm * 4 + i;
        float4 w0 = *(const float4*)&w_out[(size_t)m * HH + n0 + tn * 4];
        float4 v = make_float4(acc[i][0] + w0.x, acc[i][1] + w0.y,
                               acc[i][2] + w0.z, acc[i][3] + w0.w);
        *(float4*)&g_wp[((size_t)b * AA + m) * HH + n0 + tn * 4] = v;
    }
}

// ---------------- kernel 3: persistent recurrent loop (all 512 steps) ----------------
// 128 CTAs = 32 unit-groups x 4 batch-groups; 512 threads (16 warps).
// Warps = 8 ksg x 2 row-halves; lanes = 8 row-quads x 4 batch-quads; thread 4r x 4b.
// w smem layout bank-interleaved so all 4 LDS.128/kp are conflict-free.
// Non-aliased rbuf (stride-padded); 4 syncs/step; g_hall off the critical path.
__global__ __launch_bounds__(512) void k_loop(const float* __restrict__ w_hh,
                                              const float* __restrict__ c0) {
    extern __shared__ char smraw[];
    ull*        w2u   = (ull*)smraw;                   // [256 kp][64 slots]  131072 B
    ull*        hs2u  = (ull*)(smraw + 131072);        // [256 kp][16 b]      32768 B
    ull*        rbufU = (ull*)(smraw + 163840);        // [8 j][1032 ull]     66048 B
    ulonglong2* rbuf2 = (ulonglong2*)(smraw + 163840);

    const int tid = threadIdx.x;
    const int bid = blockIdx.x;
    const int jg  = bid & 31;        // unit group -> units j0..j0+15
    const int bgc = bid >> 5;        // batch group -> batches b0..b0+15
    const int j0  = jg * 16;
    const int b0  = bgc * 16;

    // ---- load w (kpair-packed, bank-interleaved slots) ----
    // row rr (0..63) = gate*16 + ju; rh = rr>>5, rl = rr&31,
    // slot = ((rl>>1)&1)*16 + (rl>>2)*2 + (rl&1)
    for (int idx = tid; idx < 64 * 256; idx += 512) {
        int rr = idx & 63, kp = idx >> 6;
        int gate = rr >> 4, ju = rr & 15;
        float2 wv = *(const float2*)(w_hh + (size_t)(gate * HH + j0 + ju) * HH + 2 * kp);
        ull v;
        asm("mov.b64 %0, {%1,%2};" : "=l"(v) : "f"(wv.x), "f"(wv.y));
        int rh = rr >> 5, rl = rr & 31;
        int slot = ((rl >> 1) & 1) * 16 + (rl >> 2) * 2 + (rl & 1);
        w2u[kp * 64 + rh * 32 + slot] = v;
    }

    // ---- GEMM mapping: warp = ksg*2 + rh; lane = rql*4 + bgl ----
    const int lane = tid & 31;
    const int warp = tid >> 5;
    const int ksg  = warp >> 1;      // 0..7 (32 kp each)
    const int rh   = warp & 1;       // row half (32 rows)
    const int rql  = lane >> 2;      // row quad 0..7
    const int bgl  = lane & 3;       // batch quad 0..3

    // ---- finalize+pointwise mapping (tid < 256): thread owns (pb, pu) ----
    const int pb = tid & 15, pu = tid >> 4;   // valid for tid<256
    const bool pact = (tid < 256);
    float c_reg = 0.f;
    if (pact) c_reg = c0[(size_t)(b0 + pb) * HH + j0 + pu];
    const int hT_off = ((j0 + pu) >> 1) * 128 + (b0 + pb) * 2 + ((j0 + pu) & 1);
    const int fin_bgl = pb >> 2;
    const int fin_bp  = (pb >> 1) & 1;
    const int fin_par = pb & 1;

    const unsigned e0 = ld_acq(&g_flag[bid]);
    __syncthreads();

    for (int t = 0; t < TT; ++t) {
        // prefetch pre (static data; no dependence on flags)
        float pr[4];
        if (pact) {
#pragma unroll
            for (int g = 0; g < 4; g++)
                pr[g] = __ldg(&g_pre[((size_t)t * G4 + g * HH + j0 + pu) * BB + b0 + pb]);
        }

        if (t > 0) {   // wait for the 32 CTAs of this batch domain
            if (tid < 32) {
                const unsigned target = e0 + (unsigned)t;
                const unsigned* fp = &g_flag[bgc * 32 + tid];
                while ((int)(ld_acq(fp) - target) < 0) {}
            }
            __syncthreads();
        }
        const ulonglong2* hsrc = (const ulonglong2*)g_hT2[t & 1];

        // ---- stage h slice (32 KB): 4x LDG.128 -> STS.128, coalesced ----
        {
            ulonglong2 v[4];
#pragma unroll
            for (int i = 0; i < 4; ++i) {
                int idx2 = tid + i * 512;                 // 0..2047
                int kp = idx2 >> 3, blp = idx2 & 7;
                v[i] = __ldcg(hsrc + kp * 32 + bgc * 8 + blp);
            }
#pragma unroll
            for (int i = 0; i < 4; ++i) {
                int idx2 = tid + i * 512;
                int kp = idx2 >> 3, blp = idx2 & 7;
                *(ulonglong2*)(hs2u + kp * 16 + blp * 2) = v[i];
            }
        }
        __syncthreads();

        // ---- GEMM: 32 kp per thread, 16 fma2 per kp; all LDS conflict-free ----
        ull acc[4][4];
#pragma unroll
        for (int r = 0; r < 4; r++)
#pragma unroll
            for (int b = 0; b < 4; b++) acc[r][b] = 0ull;
        {
            const ull* hp = hs2u + (ksg * 32) * 16 + bgl * 4;
            const ull* wp = w2u + (size_t)(ksg * 32) * 64 + rh * 32 + rql * 2;
#pragma unroll 8
            for (int kp = 0; kp < 32; ++kp) {
                ulonglong2 h01 = *(const ulonglong2*)(hp + kp * 16);
                ulonglong2 h23 = *(const ulonglong2*)(hp + kp * 16 + 2);
                ulonglong2 w01 = *(const ulonglong2*)(wp + kp * 64);        // rows rql*4+{0,1}
                ulonglong2 w23 = *(const ulonglong2*)(wp + kp * 64 + 16);   // rows rql*4+{2,3}
                ull hv[4] = {h01.x, h01.y, h23.x, h23.y};
                ull wv[4] = {w01.x, w01.y, w23.x, w23.y};
#pragma unroll
                for (int r = 0; r < 4; r++)
#pragma unroll
                    for (int b = 0; b < 4; b++)
                        acc[r][b] = fma2(hv[b], wv[r], acc[r][b]);
            }
        }

        // ---- publish partials (no alias -> no pre-sync): rbuf2[j*516 + tid] ----
        {
            ulonglong2* rp = rbuf2 + tid;
#pragma unroll
            for (int r = 0; r < 4; r++)
#pragma unroll
                for (int bp = 0; bp < 2; bp++)
                    rp[(r * 2 + bp) * 516] = make_ulonglong2(acc[r][bp * 2], acc[r][bp * 2 + 1]);
        }
        __syncthreads();

        // ---- merged finalize + LSTM pointwise (tid < 256) ----
        if (pact) {
            float gv[4];
#pragma unroll
            for (int g = 0; g < 4; g++) {
                const int row  = g * 16 + pu;
                const int rhf  = row >> 5;
                const int rqlf = (row >> 2) & 7;
                const int ri   = row & 3;
                const int j    = ri * 2 + fin_bp;
                const ull* base = rbufU + (size_t)j * 1032 + rhf * 64 + rqlf * 8
                                  + fin_bgl * 2 + fin_par;
                ull s = base[0];
#pragma unroll
                for (int ks = 1; ks < 8; ++ks)
                    s = add2(s, base[ks * 128]);
                float2 u = unpack2(s);
                gv[g] = u.x + u.y + pr[g];
            }
            float si = fsigmoid(gv[0]);
            float sf = fsigmoid(gv[1]);
            float tg = ftanh(gv[2]);
            float so = fsigmoid(gv[3]);
            c_reg = sf * c_reg + si * tg;
            float hn = so * ftanh(c_reg);
            __stcg((float*)g_hT2[(t + 1) & 1] + hT_off, hn);
            __syncthreads();
            if (tid == 0) st_rel(&g_flag[bid], e0 + (unsigned)(t + 1));
            // h history off the critical path (only k_out consumes it)
            __stcg(&g_hall[(size_t)t * BB * HH + (size_t)(b0 + pb) * HH + j0 + pu], hn);
        } else {
            __syncthreads();
        }
    }
}

// ---------------- kernel 4: out[b][t][a] = h_all[t][b] . W'[b][a] + b_out[a] (f32x2) ----
__global__ __launch_bounds__(256) void k_out(const float* __restrict__ b_out,
                                             float* __restrict__ out) {
    __shared__ float As[64][68];
    __shared__ float Bs[64][68];
    const int b  = blockIdx.z;
    const int m0 = blockIdx.y * 64;
    const int n0 = blockIdx.x * 64;
    const int tid = threadIdx.x;
    const int tm = tid >> 4, tn = tid & 15;
    ull acc2[4][4] = {};

    for (int k0 = 0; k0 < HH; k0 += 64) {
#pragma unroll
        for (int i = 0; i < 4; i++) {
            int id = tid + i * 256;
            int r = id >> 4, c4 = (id & 15) << 2;
            *(float4*)&As[r][c4] = *(const float4*)&g_hall[((size_t)(m0 + r) * BB + b) * HH + k0 + c4];
            *(float4*)&Bs[r][c4] = *(const float4*)&g_wp[((size_t)b * AA + n0 + r) * HH + k0 + c4];
        }
        __syncthreads();
#pragma unroll
        for (int k = 0; k < 64; k += 4) {
            ulonglong2 a[4], bv[4];
#pragma unroll
            for (int i = 0; i < 4; i++) a[i] = *(const ulonglong2*)&As[tm * 4 + i][k];
#pragma unroll
            for (int j = 0; j < 4; j++) bv[j] = *(const ulonglong2*)&Bs[tn * 4 + j][k];
#pragma unroll
            for (int i = 0; i < 4; i++)
#pragma unroll
                for (int j = 0; j < 4; j++) {
                    acc2[i][j] = fma2(a[i].x, bv[j].x, acc2[i][j]);
                    acc2[i][j] = fma2(a[i].y, bv[j].y, acc2[i][j]);
                }
        }
        __syncthreads();
    }
    float4 bo = *(const float4*)&b_out[n0 + tn * 4];
    float bb[4] = {bo.x, bo.y, bo.z, bo.w};
#pragma unroll
    for (int i = 0; i < 4; i++) {
        float r[4];
#pragma unroll
        for (int j = 0; j < 4; j++) {
            float2 u = unpack2(acc2[i][j]);
            r[j] = u.x + u.y + bb[j];
        }
        int m = m0 + tm * 4 + i;
        *(float4*)&out[((size_t)b * TT + m) * AA + n0 + tn * 4] =
            make_float4(r[0], r[1], r[2], r[3]);
    }
}

// ---------------- launch ----------------
extern "C" void kernel_launch(void* const* d_in, const int* in_sizes, int n_in,
                              void* d_out, int out_size) {
    const float* x     = (const float*)d_in[0];
    const float* w_ih  = (const float*)d_in[1];
    const float* w_hh  = (const float*)d_in[2];
    const float* b_ih  = (const float*)d_in[3];
    const float* b_hh  = (const float*)d_in[4];
    const float* Mm    = (const float*)d_in[5];
    const float* w_out = (const float*)d_in[6];
    const float* b_out = (const float*)d_in[7];
    const float* h0    = (const float*)d_in[8];
    const float* c0    = (const float*)d_in[9];
    float* out = (float*)d_out;

    const int loop_smem = 131072 + 32768 + 66048;  // 229888 B (<= 227KB cap)
    static int attr_done = 0;
    if (!attr_done) {
        cudaFuncSetAttribute(k_loop, cudaFuncAttributeMaxDynamicSharedMemorySize, loop_smem);
        attr_done = 1;
    }

    k_init<<<64, 256>>>(h0);
    k_pregates<<<dim3(G4 / 64, TT), 256>>>(x, w_ih, b_ih, b_hh);
    k_wprime<<<dim3(HH / 64, AA / 64, BB), 256>>>(w_out, Mm);

    k_loop<<<NCTA, 512, loop_smem>>>(w_hh, c0);

    k_out<<<dim3(AA / 64, TT / 64, BB), 256>>>(b_out, out);
}